// round 13
// baseline (speedup 1.0000x reference)
#include <cuda_runtime.h>
#include <math.h>

#define BATCH 256
#define TLEN  256
#define HID   256
#define G3    768   // 3*H
#define NCTA  128
#define NTHR  256
#define NPHASE 512

// ---- packed fp32x2 helpers (Blackwell FFMA2 path; PTX-only) ----
#define PACK2(out, lo, hi) \
    asm("mov.b64 %0, {%1, %2};" : "=l"(out) : "r"(__float_as_uint(lo)), "r"(__float_as_uint(hi)))
#define DUP2(out, v) \
    asm("mov.b64 %0, {%1, %1};" : "=l"(out) : "r"(__float_as_uint(v)))
#define FMA2(acc, a, b) \
    asm("fma.rn.f32x2 %0, %1, %2, %0;" : "+l"(acc) : "l"(a), "l"(b))
#define ADD2(acc, a) \
    asm("add.rn.f32x2 %0, %1, %0;" : "+l"(acc) : "l"(a))
#define UNPACK2(lo, hi, in) do { unsigned _ulo, _uhi; \
    asm("mov.b64 {%0, %1}, %2;" : "=r"(_ulo), "=r"(_uhi) : "l"(in)); \
    lo = __uint_as_float(_ulo); hi = __uint_as_float(_uhi); } while (0)

typedef unsigned long long u64t;

// Scratch (device globals — no allocation)
__device__ float g_gx0[BATCH * TLEN * G3];
__device__ float g_gx1[BATCH * TLEN * G3];
__device__ float g_h0[2][BATCH * HID];
__device__ float g_h1[2][BATCH * HID];
__device__ unsigned g_arrive;
__device__ volatile unsigned g_release;

// ---------------------------------------------------------------------------
__global__ void init_state(const float* __restrict__ hx0, const float* __restrict__ hx1) {
    int i = blockIdx.x * blockDim.x + threadIdx.x;
    if (i == 0) { g_arrive = 0u; g_release = 0u; }
    if (i < BATCH * HID) {
        g_h0[0][i] = hx0[i];
        g_h0[1][i] = hx0[i];
        g_h1[0][i] = hx1[i];
        g_h1[1][i] = hx1[i];
    }
}

// ---------------------------------------------------------------------------
// Precompute: gx[m][j] = mask[m] * sum_k x[m][k]*W[j][k] + b_ih[j]
// Inner loop rewritten with packed f32x2 FMAs (pair over m, dup over j).
// ---------------------------------------------------------------------------
__global__ __launch_bounds__(256) void precompute_kernel(
    const float* __restrict__ x, const float* __restrict__ W,
    const float* __restrict__ bias,
    const int* __restrict__ dx, const int* __restrict__ dxlz, int layer)
{
    __shared__ float As[16][128];
    __shared__ float Bs[16][64];

    float* gx = layer ? g_gx1 : g_gx0;
    int mBase = blockIdx.x * 128;
    int jBase = blockIdx.y * 64;
    int tid = threadIdx.x;
    int tmi = tid & 15;
    int tji = tid >> 4;

    u64t accP[4][4];   // [m-pair][j], packed over adjacent m
#pragma unroll
    for (int i = 0; i < 4; i++)
#pragma unroll
        for (int j = 0; j < 4; j++) accP[i][j] = 0ull;

    for (int kk = 0; kk < 256; kk += 16) {
        __syncthreads();
#pragma unroll
        for (int i = 0; i < 2; i++) {
            int idx = tid + i * 256;
            int m   = idx & 127;
            int k4  = idx >> 7;
            int mg  = mBase + m;
            float msk;
            if (layer == 0) msk = (float)dxlz[mg];
            else            msk = (float)dx[((mg >> 8) << 9) + (mg & 255)];
            float4 v = *(const float4*)(x + (size_t)mg * 256 + kk + k4 * 4);
            As[k4 * 4 + 0][m] = v.x * msk;
            As[k4 * 4 + 1][m] = v.y * msk;
            As[k4 * 4 + 2][m] = v.z * msk;
            As[k4 * 4 + 3][m] = v.w * msk;
        }
        {
            int j  = tid & 63;
            int k4 = tid >> 6;
            float4 v = *(const float4*)(W + (size_t)(jBase + j) * 512 + kk + k4 * 4);
            Bs[k4 * 4 + 0][j] = v.x;
            Bs[k4 * 4 + 1][j] = v.y;
            Bs[k4 * 4 + 2][j] = v.z;
            Bs[k4 * 4 + 3][j] = v.w;
        }
        __syncthreads();
#pragma unroll
        for (int k = 0; k < 16; k++) {
            float4 a0 = *(const float4*)&As[k][tmi * 8];
            float4 a1 = *(const float4*)&As[k][tmi * 8 + 4];
            float4 bv = *(const float4*)&Bs[k][tji * 4];
            u64t p[4], d[4];
            PACK2(p[0], a0.x, a0.y);
            PACK2(p[1], a0.z, a0.w);
            PACK2(p[2], a1.x, a1.y);
            PACK2(p[3], a1.z, a1.w);
            DUP2(d[0], bv.x);
            DUP2(d[1], bv.y);
            DUP2(d[2], bv.z);
            DUP2(d[3], bv.w);
#pragma unroll
            for (int ip = 0; ip < 4; ip++)
#pragma unroll
                for (int j = 0; j < 4; j++) FMA2(accP[ip][j], p[ip], d[j]);
        }
    }

    float4 bb = *(const float4*)(bias + jBase + tji * 4);
#pragma unroll
    for (int ip = 0; ip < 4; ip++) {
        float lo[4], hi[4];
#pragma unroll
        for (int j = 0; j < 4; j++) UNPACK2(lo[j], hi[j], accP[ip][j]);
        int m0 = mBase + tmi * 8 + 2 * ip;
        float4 o0, o1;
        o0.x = lo[0] + bb.x; o0.y = lo[1] + bb.y; o0.z = lo[2] + bb.z; o0.w = lo[3] + bb.w;
        o1.x = hi[0] + bb.x; o1.y = hi[1] + bb.y; o1.z = hi[2] + bb.z; o1.w = hi[3] + bb.w;
        *(float4*)(gx + (size_t)m0 * G3 + jBase + tji * 4) = o0;
        *(float4*)(gx + (size_t)(m0 + 1) * G3 + jBase + tji * 4) = o1;
    }
}

// ---------------------------------------------------------------------------
// Persistent recurrence kernel. 128 CTAs x 256 threads (split-K halves).
// Inner GEMM uses packed f32x2 FMAs: accumulators packed over the u-pair,
// weights loaded as ready-packed u64 pairs (layout [l][k][u-pair(8)][12]).
// smem: sW 192KB + sH 2 x 16KB = 224KB.
// ---------------------------------------------------------------------------
#define SW_SIZE    49152
#define SH_OFF     49152
#define SMEM_BYTES ((SW_SIZE + 8192) * 4)

__device__ __forceinline__ void phase_ptrs(int ph, const float*& hA, const float*& hB,
                                           float*& hOut, const float*& gx) {
    int t = ph >> 1, l = ph & 1, p = t & 1, pn = p ^ 1;
    if (l == 0) { hA = g_h1[p];  hB = g_h0[p]; hOut = g_h0[pn]; gx = g_gx0; }
    else        { hA = g_h0[pn]; hB = g_h1[p]; hOut = g_h1[pn]; gx = g_gx1; }
}

__global__ __launch_bounds__(NTHR, 1) void persistent_kernel(
    const float* __restrict__ Wih0, const float* __restrict__ Whh0,
    const float* __restrict__ bhh0,
    const float* __restrict__ Wih1, const float* __restrict__ Whh1,
    const float* __restrict__ bhh1,
    const int* __restrict__ dx, const int* __restrict__ dxlz,
    float* __restrict__ out)
{
    extern __shared__ float sm[];
    float* sW = sm;
    float* sH = sm + SH_OFF;     // two 4096-float buffers

    int tid   = threadIdx.x;
    int uTile = (blockIdx.x >> 3) * 16;
    int bTile = (blockIdx.x & 7) * 32;
    int half  = tid >> 7;
    int t128  = tid & 127;
    int tb = t128 & 15;
    int tu = t128 >> 4;
    int kBase = half * 128;

    // ---- one-time: stage resident weights (repacked [l][k][u-pair(8)][12]) ----
    for (int i = tid; i < SW_SIZE; i += NTHR) {
        int k  = i & 255;
        int r2 = i >> 12;
        int u  = (i >> 8) & 15;
        int g  = r2 % 3;
        int m  = (r2 / 3) & 1;
        int l  = r2 / 6;
        int row = g * 256 + uTile + u;
        float v;
        if (m == 0) {
            const float* W = l ? Wih1 : Wih0;
            v = W[(size_t)row * 512 + 256 + k];
        } else {
            const float* W = l ? Whh1 : Whh0;
            v = W[(size_t)row * 256 + k];
        }
        sW[((l * 256 + k) * 8 + (u >> 1)) * 12 + m * 6 + g * 2 + (u & 1)] = v;
    }

    // ---- biases in registers ----
    float rb0g[3][2], rb1g[3][2];
#pragma unroll
    for (int g = 0; g < 3; g++)
#pragma unroll
        for (int ui = 0; ui < 2; ui++) {
            int u = g * 256 + uTile + tu * 2 + ui;
            rb0g[g][ui] = bhh0[u];
            rb1g[g][ui] = bhh1[u];
        }
    __syncthreads();

    // staging geometry
    int b_s = t128 & 31;
    int k4base = (t128 >> 5);
    const size_t hOffA = (size_t)(bTile + b_s) * HID + kBase + k4base * 4;
    const size_t hOffB = (size_t)(bTile + b_s) * HID + kBase + (k4base + 4) * 4;
    int bMine = bTile + tb * 2 + half;
    int uMine = uTile + tu * 2;
    int keepBase = half * 6;          // u64 acc base kept by this thread
    int sendBase = 6 - keepBase;

    // ---- prologue: prefetch phase 0 operands ----
    float4 rnb0, rnb1;
    float pgx[3][2], phb[2], mAv, fBv;
    int byp;
    {
        const float *hA, *hB, *gx; float* hOut;
        phase_ptrs(0, hA, hB, hOut, gx);
        rnb0 = __ldcg((const float4*)(hB + hOffA));
        rnb1 = __ldcg((const float4*)(hB + hOffB));
        int b0  = dxlz[bMine * TLEN + 0];
        mAv = 0.0f; fBv = 1.0f; byp = (b0 == 0);
        const float* gxr = gx + (size_t)(bMine * TLEN + 0) * G3;
        float2 v0 = __ldcg((const float2*)(gxr + uMine));
        float2 v1 = __ldcg((const float2*)(gxr + 256 + uMine));
        float2 v2 = __ldcg((const float2*)(gxr + 512 + uMine));
        pgx[0][0] = v0.x; pgx[0][1] = v0.y;
        pgx[1][0] = v1.x; pgx[1][1] = v1.y;
        pgx[2][0] = v2.x; pgx[2][1] = v2.y;
        float2 hv = __ldcg((const float2*)(hB + (size_t)bMine * HID + uMine));
        phb[0] = hv.x; phb[1] = hv.y;
    }

#pragma unroll 1
    for (int ph = 0; ph < NPHASE; ph++) {
        int t = ph >> 1, l = ph & 1;
        const float *hA, *hB, *gx; float* hOut;
        phase_ptrs(ph, hA, hB, hOut, gx);

        // ---- post-barrier: load fresh hA chunk0, stage chunk0 to buf0 ----
        float4 ra0 = __ldcg((const float4*)(hA + hOffA));
        float4 ra1 = __ldcg((const float4*)(hA + hOffB));
        {
            float* base = sH + half * 2048;
            float* dA0 = base + (k4base * 4) * 32 + b_s;
            float* dA1 = base + ((k4base + 4) * 4) * 32 + b_s;
            float* dB0 = dA0 + 1024;
            float* dB1 = dA1 + 1024;
            dA0[0]=ra0.x;  dA0[32]=ra0.y;  dA0[64]=ra0.z;  dA0[96]=ra0.w;
            dA1[0]=ra1.x;  dA1[32]=ra1.y;  dA1[64]=ra1.z;  dA1[96]=ra1.w;
            dB0[0]=rnb0.x; dB0[32]=rnb0.y; dB0[64]=rnb0.z; dB0[96]=rnb0.w;
            dB1[0]=rnb1.x; dB1[32]=rnb1.y; dB1[64]=rnb1.z; dB1[96]=rnb1.w;
        }
        __syncthreads();

        // acc[bi*6 + 0..2] = accI gates r,z,n ; acc[bi*6 + 3..5] = accH
        // each u64 packed over the u-pair (lo=u0, hi=u1)
        u64t acc[12];
#pragma unroll
        for (int j = 0; j < 12; j++) acc[j] = 0ull;

        float4 rg[4];
#pragma unroll 1
        for (int c = 0; c < 4; c++) {
            if (c < 3) {
                int koff = (c + 1) * 32;
                rg[0] = __ldcg((const float4*)(hA + hOffA + koff));
                rg[1] = __ldcg((const float4*)(hA + hOffB + koff));
                rg[2] = __ldcg((const float4*)(hB + hOffA + koff));
                rg[3] = __ldcg((const float4*)(hB + hOffB + koff));
            }
            const float* sa = sH + (c & 1) * 4096 + half * 2048;
            const float* sb = sa + 1024;
            const float* wbase = sW + ((size_t)(l * 256 + kBase + c * 32) * 8 + tu) * 12;
#pragma unroll
            for (int k = 0; k < 32; k++) {
                float2 a  = *(const float2*)(sa + k * 32 + tb * 2);
                float2 hb = *(const float2*)(sb + k * 32 + tb * 2);
                u64t ax2, ay2, hx2, hy2;
                DUP2(ax2, a.x); DUP2(ay2, a.y);
                DUP2(hx2, hb.x); DUP2(hy2, hb.y);
                const ulonglong2* w = (const ulonglong2*)(wbase + k * 96);
                ulonglong2 wA = w[0];   // {Wi g0 pair, Wi g1 pair}
                ulonglong2 wB = w[1];   // {Wi g2 pair, Wh g0 pair}
                ulonglong2 wC = w[2];   // {Wh g1 pair, Wh g2 pair}
                FMA2(acc[0],  ax2, wA.x);
                FMA2(acc[1],  ax2, wA.y);
                FMA2(acc[2],  ax2, wB.x);
                FMA2(acc[3],  hx2, wB.y);
                FMA2(acc[4],  hx2, wC.x);
                FMA2(acc[5],  hx2, wC.y);
                FMA2(acc[6],  ay2, wA.x);
                FMA2(acc[7],  ay2, wA.y);
                FMA2(acc[8],  ay2, wB.x);
                FMA2(acc[9],  hy2, wB.y);
                FMA2(acc[10], hy2, wC.x);
                FMA2(acc[11], hy2, wC.y);
            }
            if (c < 3) {
                float* base = sH + ((c + 1) & 1) * 4096 + half * 2048;
                float* dA0 = base + (k4base * 4) * 32 + b_s;
                float* dA1 = base + ((k4base + 4) * 4) * 32 + b_s;
                float* dB0 = dA0 + 1024;
                float* dB1 = dA1 + 1024;
                dA0[0]=rg[0].x; dA0[32]=rg[0].y; dA0[64]=rg[0].z; dA0[96]=rg[0].w;
                dA1[0]=rg[1].x; dA1[32]=rg[1].y; dA1[64]=rg[1].z; dA1[96]=rg[1].w;
                dB0[0]=rg[2].x; dB0[32]=rg[2].y; dB0[64]=rg[2].z; dB0[96]=rg[2].w;
                dB1[0]=rg[3].x; dB1[32]=rg[3].y; dB1[64]=rg[3].z; dB1[96]=rg[3].w;
                __syncthreads();
            }
        }

        // ---- split-K exchange (u64 packed partials) ----
        // chunk-3 compute read buf1; sRed lives in buf0 — disjoint, no sync needed
        u64t* sRedU = (u64t*)sH;
        {
            u64t* wr = sRedU + half * 768 + t128 * 6;
#pragma unroll
            for (int j = 0; j < 6; j++) wr[j] = acc[sendBase + j];
        }
        __syncthreads();
        {
            const u64t* rd = sRedU + (half ^ 1) * 768 + t128 * 6;
#pragma unroll
            for (int j = 0; j < 6; j++) ADD2(acc[keepBase + j], rd[j]);
        }

        // ---- epilogue: this thread's single batch row, 2 u outputs ----
        float aIlo[3], aIhi[3], aHlo[3], aHhi[3];
#pragma unroll
        for (int g = 0; g < 3; g++) {
            UNPACK2(aIlo[g], aIhi[g], acc[keepBase + g]);
            UNPACK2(aHlo[g], aHhi[g], acc[keepBase + 3 + g]);
        }
        float res2[2];
#pragma unroll
        for (int ui = 0; ui < 2; ui++) {
            float aI0 = ui ? aIhi[0] : aIlo[0];
            float aI1 = ui ? aIhi[1] : aIlo[1];
            float aI2 = ui ? aIhi[2] : aIlo[2];
            float aH0 = ui ? aHhi[0] : aHlo[0];
            float aH1 = ui ? aHhi[1] : aHlo[1];
            float aH2 = ui ? aHhi[2] : aHlo[2];
            float hUsed = phb[ui] * fBv;
            float giR = pgx[0][ui] + mAv * aI0;
            float giZ = pgx[1][ui] + mAv * aI1;
            float giN = pgx[2][ui] + mAv * aI2;
            float bR = l ? rb1g[0][ui] : rb0g[0][ui];
            float bZ = l ? rb1g[1][ui] : rb0g[1][ui];
            float bN = l ? rb1g[2][ui] : rb0g[2][ui];
            float ghR = bR + fBv * aH0;
            float ghZ = bZ + fBv * aH1;
            float ghN = bN + fBv * aH2;
            float r = 1.0f / (1.0f + expf(-(giR + ghR)));
            float z = 1.0f / (1.0f + expf(-(giZ + ghZ)));
            float n = tanhf(giN + r * ghN);
            float hnew = (1.0f - z) * n + z * hUsed;
            res2[ui] = byp ? hUsed : hnew;
        }
        float2 rv; rv.x = res2[0]; rv.y = res2[1];
        __stcg((float2*)(hOut + (size_t)bMine * HID + uMine), rv);

        // ---- arrive ASAP; defer out-store + prefetch to the wait window ----
        __threadfence();
        __syncthreads();
        unsigned target = (unsigned)(ph + 1);
        if (tid == 0) {
            unsigned v = atomicAdd(&g_arrive, 1u) + 1u;
            if (v == (unsigned)NCTA * target) g_release = target;
        }

        __stcg((float2*)(out + (((size_t)l * BATCH + bMine) * TLEN + t) * HID + uMine), rv);

        if (ph + 1 < NPHASE) {
            int q = ph + 1, tq = q >> 1, lq = q & 1;
            const float *hAq, *hBq, *gxq; float* hOq;
            phase_ptrs(q, hAq, hBq, hOq, gxq);
            rnb0 = __ldcg((const float4*)(hBq + hOffA));
            rnb1 = __ldcg((const float4*)(hBq + hOffB));
            if (lq == 0) {
                int b0  = dxlz[bMine * TLEN + tq];
                int dd0 = dx[(bMine * 2) * TLEN + tq - 1];
                mAv = (float)dd0; fBv = 1.0f - (float)dd0; byp = (b0 + dd0 == 0);
            } else {
                int b1  = dx[(bMine * 2) * TLEN + tq];
                int dd1 = (tq > 0) ? dx[(bMine * 2 + 1) * TLEN + tq - 1] : 0;
                mAv = (float)b1; fBv = 1.0f - (float)dd1; byp = (b1 + dd1 == 0);
            }
            const float* gxr = gxq + (size_t)(bMine * TLEN + tq) * G3;
            float2 v0 = __ldcg((const float2*)(gxr + uMine));
            float2 v1 = __ldcg((const float2*)(gxr + 256 + uMine));
            float2 v2 = __ldcg((const float2*)(gxr + 512 + uMine));
            pgx[0][0] = v0.x; pgx[0][1] = v0.y;
            pgx[1][0] = v1.x; pgx[1][1] = v1.y;
            pgx[2][0] = v2.x; pgx[2][1] = v2.y;
            float2 hv = __ldcg((const float2*)(hBq + (size_t)bMine * HID + uMine));
            phb[0] = hv.x; phb[1] = hv.y;

            if (tid == 0) {
                while (g_release < target) __nanosleep(32);
            }
            __syncthreads();
        }
    }
}

// ---------------------------------------------------------------------------
extern "C" void kernel_launch(void* const* d_in, const int* in_sizes, int n_in,
                              void* d_out, int out_size) {
    const float* x0    = (const float*)d_in[0];
    const float* x1    = (const float*)d_in[1];
    const float* hx0   = (const float*)d_in[2];
    const float* hx1   = (const float*)d_in[3];
    const float* W_ih0 = (const float*)d_in[4];
    const float* W_hh0 = (const float*)d_in[5];
    const float* b_ih0 = (const float*)d_in[6];
    const float* b_hh0 = (const float*)d_in[7];
    const float* W_ih1 = (const float*)d_in[8];
    const float* W_hh1 = (const float*)d_in[9];
    const float* b_ih1 = (const float*)d_in[10];
    const float* b_hh1 = (const float*)d_in[11];
    const int*   dx    = (const int*)d_in[12];
    const int*   dxlz  = (const int*)d_in[13];
    float* out = (float*)d_out;

    cudaFuncSetAttribute(persistent_kernel,
                         cudaFuncAttributeMaxDynamicSharedMemorySize, SMEM_BYTES);

    init_state<<<256, 256>>>(hx0, hx1);

    dim3 pgrid(512, 12);
    precompute_kernel<<<pgrid, 256>>>(x0, W_ih0, b_ih0, dx, dxlz, 0);
    precompute_kernel<<<pgrid, 256>>>(x1, W_ih1, b_ih1, dx, dxlz, 1);

    persistent_kernel<<<NCTA, NTHR, SMEM_BYTES>>>(
        W_ih0, W_hh0, b_hh0, W_ih1, W_hh1, b_hh1, dx, dxlz, out);
}